// round 2
// baseline (speedup 1.0000x reference)
#include <cuda_runtime.h>
#include <cuda_bf16.h>
#include <math.h>

// Problem constants
#define B   32
#define LQ  64
#define LK  256
#define D   128
#define NN  32          // negatives
#define NC  (NN + 1)    // candidates per batch (pos + negs)
#define TINV 20.0f      // 1 / 0.05

// Device scratch for per-(b,candidate) logits
__device__ float g_logits[B * NC];

// Shared memory layout (floats):
//   As   : [64][128]          = 8192
//   Bs   : [32][256] (k-major)= 8192
//   invk : [256]
//   invq : [64]
//   wred : [8]
#define SM_AS    0
#define SM_BS    (64 * 128)
#define SM_INVK  (SM_BS + 32 * 256)
#define SM_INVQ  (SM_INVK + 256)
#define SM_WRED  (SM_INVQ + 64)
#define SM_TOTAL (SM_WRED + 8)
#define SMEM_BYTES (SM_TOTAL * sizeof(float))

__global__ __launch_bounds__(256, 2)
void maxsim_scores_kernel(const float* __restrict__ query,
                          const float* __restrict__ pos_key,
                          const float* __restrict__ neg_key)
{
    extern __shared__ float sm[];
    float* As   = sm + SM_AS;     // [64][128] row-major (q rows)
    float* Bs   = sm + SM_BS;     // [32][256] k-major chunk (Bs[kk][key])
    float* invk = sm + SM_INVK;   // [256]
    float* invq = sm + SM_INVQ;   // [64]
    float* wred = sm + SM_WRED;   // [8]

    const int bidx = blockIdx.x;
    const int b = bidx / NC;
    const int j = bidx % NC;

    const float* qptr = query + (size_t)b * LQ * D;
    const float* kptr = (j == 0)
        ? (pos_key + (size_t)b * LK * D)
        : (neg_key + ((size_t)(b * NN + (j - 1))) * LK * D);

    const int tid = threadIdx.x;
    const int ctx = tid & 31;   // column tile 0..31 -> cols [ctx*8, ctx*8+8)
    const int cty = tid >> 5;   // row tile 0..7    -> rows [cty*8, cty*8+8)

    // ---- Load A (query block) into smem: 2048 float4, 8 per thread ----
    {
        const float4* qs = (const float4*)qptr;
        float4* as4 = (float4*)As;
        #pragma unroll
        for (int i = 0; i < 8; i++) {
            as4[tid + i * 256] = qs[tid + i * 256];
        }
    }
    __syncthreads();

    // ---- invq: threads 0..63, sum of squares of one q row ----
    if (tid < LQ) {
        const float* r = As + tid * D;
        float ss = 0.f;
        #pragma unroll 16
        for (int k = 0; k < D; k++) ss += r[k] * r[k];
        invq[tid] = 1.0f / fmaxf(sqrtf(ss), 1e-12f);
    }

    // ---- Main GEMM loop: 4 chunks of K=32 ----
    float acc[8][8];
    #pragma unroll
    for (int i = 0; i < 8; i++)
        #pragma unroll
        for (int jj = 0; jj < 8; jj++)
            acc[i][jj] = 0.f;

    float ssk = 0.f;                      // sum of squares of key row `tid`
    const float* brow = kptr + (size_t)tid * D;

    #pragma unroll 1
    for (int chunk = 0; chunk < 4; chunk++) {
        __syncthreads();   // Bs free (prev compute done / first iter: after A load sync)

        // Load B chunk: thread t owns key row t, 32 contiguous floats
        const float4* src = (const float4*)(brow + chunk * 32);
        #pragma unroll
        for (int i4 = 0; i4 < 8; i4++) {
            float4 v = src[i4];
            ssk += v.x * v.x + v.y * v.y + v.z * v.z + v.w * v.w;
            const int c0 = i4 * 4;
            Bs[(c0 + 0) * 256 + tid] = v.x;
            Bs[(c0 + 1) * 256 + tid] = v.y;
            Bs[(c0 + 2) * 256 + tid] = v.z;
            Bs[(c0 + 3) * 256 + tid] = v.w;
        }
        __syncthreads();

        const float* abase = As + cty * 8 * D + chunk * 32;
        #pragma unroll 8
        for (int kk = 0; kk < 32; kk++) {
            float a[8];
            #pragma unroll
            for (int i = 0; i < 8; i++) a[i] = abase[i * D + kk];   // broadcast LDS
            float4 b0 = *(const float4*)(Bs + kk * 256 + ctx * 8);
            float4 b1 = *(const float4*)(Bs + kk * 256 + ctx * 8 + 4);
            float bb[8] = {b0.x, b0.y, b0.z, b0.w, b1.x, b1.y, b1.z, b1.w};
            #pragma unroll
            for (int i = 0; i < 8; i++)
                #pragma unroll
                for (int jj = 0; jj < 8; jj++)
                    acc[i][jj] = fmaf(a[i], bb[jj], acc[i][jj]);
        }
    }

    // ---- invk for key row tid ----
    invk[tid] = 1.0f / fmaxf(sqrtf(ssk), 1e-12f);
    __syncthreads();

    // ---- Epilogue: scale by invk, rowmax over 256 keys, dot with invq ----
    float ik[8];
    #pragma unroll
    for (int jj = 0; jj < 8; jj++) ik[jj] = invk[ctx * 8 + jj];

    float total = 0.f;
    #pragma unroll
    for (int i = 0; i < 8; i++) {
        float m = -INFINITY;
        #pragma unroll
        for (int jj = 0; jj < 8; jj++)
            m = fmaxf(m, acc[i][jj] * ik[jj]);
        // butterfly max across the 32 lanes (covers all 256 keys)
        #pragma unroll
        for (int off = 16; off > 0; off >>= 1)
            m = fmaxf(m, __shfl_xor_sync(0xffffffffu, m, off));
        total += m * invq[cty * 8 + i];
    }
    if (ctx == 0) wred[cty] = total;
    __syncthreads();
    if (tid == 0) {
        float s = 0.f;
        #pragma unroll
        for (int w = 0; w < 8; w++) s += wred[w];
        g_logits[b * NC + j] = s;
    }
}

__global__ void maxsim_loss_kernel(float* __restrict__ out)
{
    const int b = threadIdx.x;   // 0..31, one warp
    float mx = -INFINITY;
    float l[NC];
    #pragma unroll
    for (int j = 0; j < NC; j++) {
        l[j] = g_logits[b * NC + j] * TINV;
        mx = fmaxf(mx, l[j]);
    }
    const float l0 = l[0];
    float se = 0.f;
    #pragma unroll
    for (int j = 0; j < NC; j++) se += expf(l[j] - mx);
    float loss = (mx + logf(se)) - l0;
    // mean over batch
    #pragma unroll
    for (int off = 16; off > 0; off >>= 1)
        loss += __shfl_xor_sync(0xffffffffu, loss, off);
    if (b == 0) out[0] = loss * (1.0f / 32.0f);
}

extern "C" void kernel_launch(void* const* d_in, const int* in_sizes, int n_in,
                              void* d_out, int out_size)
{
    const float* query   = (const float*)d_in[0];
    // d_in[1] = query_mask (unused by reference)
    const float* pos_key = (const float*)d_in[2];
    // d_in[3] = pos_mask (unused)
    const float* neg_key = (const float*)d_in[4];
    // d_in[5] = neg_mask (unused)

    // Idempotent, host-side only (not a stream op -> capture-safe), no static guard.
    cudaFuncSetAttribute(maxsim_scores_kernel,
                         cudaFuncAttributeMaxDynamicSharedMemorySize,
                         (int)SMEM_BYTES);

    maxsim_scores_kernel<<<B * NC, 256, SMEM_BYTES>>>(query, pos_key, neg_key);
    maxsim_loss_kernel<<<1, 32>>>((float*)d_out);
}

// round 4
// speedup vs baseline: 1.0760x; 1.0760x over previous
#include <cuda_runtime.h>
#include <cuda_bf16.h>
#include <math.h>
#include <stdint.h>

// ---------------- problem constants ----------------
#define B_   32
#define LQ   64
#define LK   256
#define D_   128
#define NN   32
#define NC   33          // 1 pos + 32 negs
#define TINV 20.0f

// per-(b,candidate) per-query maxima (scaled by invk only)
__device__ float g_max[B_ * NC * LQ];

// ---------------- smem layout (bytes) ----------------
// padded rows: 128 bf16 = 256B data + 16B pad = 272B stride (conflict-free ldmatrix)
#define ROWB    272
#define SM_INVK 0                       // 128 floats
#define SM_RED  512                     // 4*16*2 floats
#define SM_QHI  1024                    // 64 rows
#define SM_QLO  (SM_QHI + 64 * ROWB)    // 18432
#define SM_KHI  (SM_QLO + 64 * ROWB)    // 35840, 128 rows
#define SM_KLO  (SM_KHI + 128 * ROWB)   // 70656
#define SM_BYTES (SM_KLO + 128 * ROWB)  // 105472
#define QDLO (SM_QLO - SM_QHI)
#define KDLO (SM_KLO - SM_KHI)

static __device__ __forceinline__ uint32_t smem_u32(const void* p) {
    uint32_t a;
    asm("{ .reg .u64 t; cvta.to.shared.u64 t, %1; cvt.u32.u64 %0, t; }" : "=r"(a) : "l"(p));
    return a;
}

#define LDSM_X4(r0, r1, r2, r3, a) \
    asm volatile("ldmatrix.sync.aligned.m8n8.x4.shared.b16 {%0,%1,%2,%3}, [%4];" \
                 : "=r"(r0), "=r"(r1), "=r"(r2), "=r"(r3) : "r"(a))

#define MMA16816(c, a0, a1, a2, a3, b0, b1) \
    asm volatile("mma.sync.aligned.m16n8k16.row.col.f32.bf16.bf16.f32 " \
                 "{%0,%1,%2,%3}, {%4,%5,%6,%7}, {%8,%9}, {%0,%1,%2,%3};" \
                 : "+f"((c)[0]), "+f"((c)[1]), "+f"((c)[2]), "+f"((c)[3]) \
                 : "r"(a0), "r"(a1), "r"(a2), "r"(a3), "r"(b0), "r"(b1))

// split (x,y) into packed bf16 hi and lo pairs
static __device__ __forceinline__ void cvt2(float x, float y, uint32_t& hi, uint32_t& lo) {
    __nv_bfloat16 hx = __float2bfloat16_rn(x);
    __nv_bfloat16 hy = __float2bfloat16_rn(y);
    __nv_bfloat16 lx = __float2bfloat16_rn(x - __bfloat162float(hx));
    __nv_bfloat16 ly = __float2bfloat16_rn(y - __bfloat162float(hy));
    hi = (uint32_t)__bfloat16_as_ushort(hx) | ((uint32_t)__bfloat16_as_ushort(hy) << 16);
    lo = (uint32_t)__bfloat16_as_ushort(lx) | ((uint32_t)__bfloat16_as_ushort(ly) << 16);
}

// load one 128-float row, convert, store hi/lo at padded smem row; return lane ssq
static __device__ __forceinline__ float ldcvt_row(const float* __restrict__ rowptr,
                                                  char* hi_base, char* lo_base,
                                                  int row, int lane) {
    float4 v = ((const float4*)rowptr)[lane];
    uint32_t ha, la, hb, lb;
    cvt2(v.x, v.y, ha, la);
    cvt2(v.z, v.w, hb, lb);
    const uint32_t off = (uint32_t)row * ROWB + (uint32_t)lane * 8;
    *(uint2*)(hi_base + off) = make_uint2(ha, hb);
    *(uint2*)(lo_base + off) = make_uint2(la, lb);
    return v.x * v.x + v.y * v.y + v.z * v.z + v.w * v.w;
}

__global__ __launch_bounds__(256, 2)
void maxsim_scores_kernel(const float* __restrict__ query,
                          const float* __restrict__ pos_key,
                          const float* __restrict__ neg_key)
{
    extern __shared__ __align__(1024) char smc[];
    const uint32_t sb = smem_u32(smc);
    float* invk = (float*)(smc + SM_INVK);
    float* red  = (float*)(smc + SM_RED);

    const int cj = blockIdx.x;          // b*NC + j
    const int b  = cj / NC;
    const int j  = cj % NC;

    const float* qptr = query + (size_t)b * LQ * D_;
    const float* kptr = (j == 0)
        ? (pos_key + (size_t)b * LK * D_)
        : (neg_key + ((size_t)(b * NN + (j - 1))) * LK * D_);

    const int tid  = threadIdx.x;
    const int wid  = tid >> 5;
    const int lane = tid & 31;
    const int qt   = wid & 3;           // q tile: rows qt*16..qt*16+15
    const int kh   = wid >> 2;          // key half within chunk: keys kh*64..kh*64+63

    // ---- Phase 1: load Q (64 rows) and K chunk 0 (128 rows) ----
    #pragma unroll
    for (int i = 0; i < 8; i++) {
        int row = wid + 8 * i;
        ldcvt_row(qptr + (size_t)row * D_, smc + SM_QHI, smc + SM_QLO, row, lane);
    }
    #pragma unroll
    for (int i = 0; i < 16; i++) {
        int row = wid + 8 * i;
        float ss = ldcvt_row(kptr + (size_t)row * D_, smc + SM_KHI, smc + SM_KLO, row, lane);
        #pragma unroll
        for (int o = 16; o > 0; o >>= 1) ss += __shfl_xor_sync(0xffffffffu, ss, o);
        if (lane == 0) invk[row] = 1.0f / fmaxf(sqrtf(ss), 1e-12f);
    }
    __syncthreads();

    // ldmatrix base addresses
    const uint32_t addrA = sb + SM_QHI + (uint32_t)(qt * 16 + (lane & 15)) * ROWB
                              + (uint32_t)(16 * (lane >> 4));
    const uint32_t addrB0 = sb + SM_KHI
        + (uint32_t)(kh * 64 + (lane & 7) + 8 * (lane >> 4)) * ROWB
        + (uint32_t)(16 * ((lane >> 3) & 1));

    float rm0 = -INFINITY, rm1 = -INFINITY;   // running per-q-row maxima

    #pragma unroll
    for (int c = 0; c < 2; c++) {
        float acc[8][4];
        #pragma unroll
        for (int nt = 0; nt < 8; nt++)
            #pragma unroll
            for (int e = 0; e < 4; e++)
                acc[nt][e] = 0.f;

        #pragma unroll
        for (int ks = 0; ks < 8; ks++) {
            uint32_t ah0, ah1, ah2, ah3, al0, al1, al2, al3;
            const uint32_t aA = addrA + ks * 32;
            LDSM_X4(ah0, ah1, ah2, ah3, aA);
            LDSM_X4(al0, al1, al2, al3, aA + QDLO);
            #pragma unroll
            for (int ntp = 0; ntp < 4; ntp++) {
                uint32_t bh0, bh1, bh2, bh3, bl0, bl1, bl2, bl3;
                const uint32_t aB = addrB0 + (uint32_t)(ntp * 16) * ROWB + ks * 32;
                LDSM_X4(bh0, bh1, bh2, bh3, aB);
                LDSM_X4(bl0, bl1, bl2, bl3, aB + KDLO);
                // ntile 2*ntp : B frag {bh0,bh1}; ntile 2*ntp+1 : {bh2,bh3}
                MMA16816(acc[2 * ntp],     ah0, ah1, ah2, ah3, bh0, bh1);
                MMA16816(acc[2 * ntp + 1], ah0, ah1, ah2, ah3, bh2, bh3);
                MMA16816(acc[2 * ntp],     ah0, ah1, ah2, ah3, bl0, bl1);
                MMA16816(acc[2 * ntp + 1], ah0, ah1, ah2, ah3, bl2, bl3);
                MMA16816(acc[2 * ntp],     al0, al1, al2, al3, bh0, bh1);
                MMA16816(acc[2 * ntp + 1], al0, al1, al2, al3, bh2, bh3);
            }
        }

        // scale by invk and fold into running max
        #pragma unroll
        for (int nt = 0; nt < 8; nt++) {
            const int kb = kh * 64 + nt * 8 + 2 * (lane & 3);
            const float ik0 = invk[kb];
            const float ik1 = invk[kb + 1];
            rm0 = fmaxf(rm0, fmaxf(acc[nt][0] * ik0, acc[nt][1] * ik1));
            rm1 = fmaxf(rm1, fmaxf(acc[nt][2] * ik0, acc[nt][3] * ik1));
        }
        __syncthreads();    // all ldmatrix reads + invk reads done

        if (c == 0) {
            // load K chunk 1
            #pragma unroll
            for (int i = 0; i < 16; i++) {
                int row = wid + 8 * i;
                float ss = ldcvt_row(kptr + (size_t)(128 + row) * D_,
                                     smc + SM_KHI, smc + SM_KLO, row, lane);
                #pragma unroll
                for (int o = 16; o > 0; o >>= 1) ss += __shfl_xor_sync(0xffffffffu, ss, o);
                if (lane == 0) invk[row] = 1.0f / fmaxf(sqrtf(ss), 1e-12f);
            }
            __syncthreads();
        }
    }

    // ---- reduce: max across the 4-lane column group, then across key halves ----
    #pragma unroll
    for (int o = 1; o < 4; o <<= 1) {
        rm0 = fmaxf(rm0, __shfl_xor_sync(0xffffffffu, rm0, o));
        rm1 = fmaxf(rm1, __shfl_xor_sync(0xffffffffu, rm1, o));
    }
    if ((lane & 3) == 0) {
        const int row = lane >> 2;
        red[qt * 32 + row * 2 + kh]       = rm0;
        red[qt * 32 + (row + 8) * 2 + kh] = rm1;
    }
    __syncthreads();
    if (tid < LQ) {
        const int qtl = tid >> 4, qr = tid & 15;
        float m = fmaxf(red[qtl * 32 + qr * 2], red[qtl * 32 + qr * 2 + 1]);
        g_max[(size_t)cj * LQ + tid] = m;
    }
}

// ---- finisher: invq, logits, log-softmax, mean ----
__global__ __launch_bounds__(1024)
void maxsim_loss_kernel(const float* __restrict__ query, float* __restrict__ out)
{
    __shared__ float lb[32];
    const int tid = threadIdx.x;
    const int b   = tid >> 5;     // warp per batch
    const int lid = tid & 31;
    const int q0 = lid, q1 = lid + 32;

    const float4* qr0 = (const float4*)(query + (size_t)(b * LQ + q0) * D_);
    const float4* qr1 = (const float4*)(query + (size_t)(b * LQ + q1) * D_);
    float s0 = 0.f, s1 = 0.f;
    #pragma unroll 8
    for (int i = 0; i < 32; i++) {
        float4 v = qr0[i]; s0 += v.x * v.x + v.y * v.y + v.z * v.z + v.w * v.w;
        float4 w = qr1[i]; s1 += w.x * w.x + w.y * w.y + w.z * w.z + w.w * w.w;
    }
    const float iq0 = 1.0f / fmaxf(sqrtf(s0), 1e-12f);
    const float iq1 = 1.0f / fmaxf(sqrtf(s1), 1e-12f);

    float l[NC];
    #pragma unroll
    for (int j = 0; j < NC; j++) {
        const float* gp = g_max + (size_t)(b * NC + j) * LQ;
        float s = gp[q0] * iq0 + gp[q1] * iq1;
        #pragma unroll
        for (int o = 16; o > 0; o >>= 1) s += __shfl_xor_sync(0xffffffffu, s, o);
        l[j] = s * TINV;
    }
    float mx = -INFINITY;
    #pragma unroll
    for (int j = 0; j < NC; j++) mx = fmaxf(mx, l[j]);
    float se = 0.f;
    #pragma unroll
    for (int j = 0; j < NC; j++) se += expf(l[j] - mx);
    float loss = mx + logf(se) - l[0];

    if (lid == 0) lb[b] = loss;
    __syncthreads();
    if (tid < 32) {
        float v = lb[tid];
        #pragma unroll
        for (int o = 16; o > 0; o >>= 1) v += __shfl_xor_sync(0xffffffffu, v, o);
        if (tid == 0) out[0] = v * (1.0f / 32.0f);
    }
}

extern "C" void kernel_launch(void* const* d_in, const int* in_sizes, int n_in,
                              void* d_out, int out_size)
{
    const float* query   = (const float*)d_in[0];
    const float* pos_key = (const float*)d_in[2];
    const float* neg_key = (const float*)d_in[4];

    cudaFuncSetAttribute(maxsim_scores_kernel,
                         cudaFuncAttributeMaxDynamicSharedMemorySize, SM_BYTES);

    maxsim_scores_kernel<<<B_ * NC, 256, SM_BYTES>>>(query, pos_key, neg_key);
    maxsim_loss_kernel<<<1, 1024>>>(query, (float*)d_out);
}

// round 5
// speedup vs baseline: 1.5950x; 1.4823x over previous
#include <cuda_runtime.h>
#include <cuda_bf16.h>
#include <math.h>
#include <stdint.h>

// ---------------- problem constants ----------------
#define B_   32
#define LQ   64
#define LK   256
#define D_   128
#define NN   32
#define NC   33          // 1 pos + 32 negs
#define TINV 20.0f

// per-(b,candidate) logit (pre-temperature)
__device__ float g_logits[B_ * NC];

// ---------------- smem layout (bytes) ----------------
// padded rows: 128 bf16 = 256B data + 16B pad = 272B stride (conflict-free ldmatrix)
#define ROWB    272
#define SM_INVK 0                        // 2 x 64 floats (double-buffered K norms)
#define SM_INVQ 512                      // 64 floats
#define SM_RED  768                      // 128 floats
#define SM_QHI  2048                     // 64 rows x 272B
#define SM_QLO  (SM_QHI + 64 * ROWB)     // 19456
#define SM_K0HI (SM_QLO + 64 * ROWB)     // 36864  (chunk buffer 0, 64 rows)
#define SM_K0LO (SM_K0HI + 64 * ROWB)    // 54272
#define SM_K1HI (SM_K0LO + 64 * ROWB)    // 71680  (chunk buffer 1)
#define SM_K1LO (SM_K1HI + 64 * ROWB)    // 89088
#define SM_BYTES (SM_K1LO + 64 * ROWB)   // 106496
#define DLO     (64 * ROWB)              // hi->lo offset (17408), same for Q and K

static __device__ __forceinline__ uint32_t smem_u32(const void* p) {
    uint32_t a;
    asm("{ .reg .u64 t; cvta.to.shared.u64 t, %1; cvt.u32.u64 %0, t; }" : "=r"(a) : "l"(p));
    return a;
}

#define LDSM_X4(r0, r1, r2, r3, a) \
    asm volatile("ldmatrix.sync.aligned.m8n8.x4.shared.b16 {%0,%1,%2,%3}, [%4];" \
                 : "=r"(r0), "=r"(r1), "=r"(r2), "=r"(r3) : "r"(a))

#define MMA16816(c, a0, a1, a2, a3, b0, b1) \
    asm volatile("mma.sync.aligned.m16n8k16.row.col.f32.bf16.bf16.f32 " \
                 "{%0,%1,%2,%3}, {%4,%5,%6,%7}, {%8,%9}, {%0,%1,%2,%3};" \
                 : "+f"((c)[0]), "+f"((c)[1]), "+f"((c)[2]), "+f"((c)[3]) \
                 : "r"(a0), "r"(a1), "r"(a2), "r"(a3), "r"(b0), "r"(b1))

// split (x,y) into packed bf16 hi and lo pairs
static __device__ __forceinline__ void cvt2(float x, float y, uint32_t& hi, uint32_t& lo) {
    __nv_bfloat16 hx = __float2bfloat16_rn(x);
    __nv_bfloat16 hy = __float2bfloat16_rn(y);
    __nv_bfloat16 lx = __float2bfloat16_rn(x - __bfloat162float(hx));
    __nv_bfloat16 ly = __float2bfloat16_rn(y - __bfloat162float(hy));
    hi = (uint32_t)__bfloat16_as_ushort(hx) | ((uint32_t)__bfloat16_as_ushort(hy) << 16);
    lo = (uint32_t)__bfloat16_as_ushort(lx) | ((uint32_t)__bfloat16_as_ushort(ly) << 16);
}

// convert one float4 (cols lane*4..+3 of `row`) and store hi/lo into padded smem
static __device__ __forceinline__ void cvtstore(float4 v, char* hi_base, char* lo_base,
                                                int row, int lane) {
    uint32_t ha, la, hb, lb;
    cvt2(v.x, v.y, ha, la);
    cvt2(v.z, v.w, hb, lb);
    const uint32_t off = (uint32_t)row * ROWB + (uint32_t)lane * 8;
    *(uint2*)(hi_base + off) = make_uint2(ha, hb);
    *(uint2*)(lo_base + off) = make_uint2(la, lb);
}

static __device__ __forceinline__ float ssq4(float4 v) {
    return v.x * v.x + v.y * v.y + v.z * v.z + v.w * v.w;
}

__global__ __launch_bounds__(256, 2)
void maxsim_scores_kernel(const float* __restrict__ query,
                          const float* __restrict__ pos_key,
                          const float* __restrict__ neg_key)
{
    extern __shared__ __align__(1024) char smc[];
    const uint32_t sb = smem_u32(smc);
    float* invk = (float*)(smc + SM_INVK);   // [2][64]
    float* invq = (float*)(smc + SM_INVQ);   // [64]
    float* red  = (float*)(smc + SM_RED);    // [128]

    const int cj = blockIdx.x;          // b*NC + j
    const int b  = cj / NC;
    const int j  = cj % NC;

    const float* qptr = query + (size_t)b * LQ * D_;
    const float* kptr = (j == 0)
        ? (pos_key + (size_t)b * LK * D_)
        : (neg_key + ((size_t)(b * NN + (j - 1))) * LK * D_);

    const int tid  = threadIdx.x;
    const int wid  = tid >> 5;
    const int lane = tid & 31;
    const int qt   = wid & 3;           // q tile: rows qt*16..qt*16+15
    const int kh   = wid >> 2;          // key half within 64-chunk: keys kh*32..+31

    // ---- Prologue: Q load+cvt (+invq), K chunk 0 load+cvt (+invk[0]) ----
    #pragma unroll
    for (int i = 0; i < 8; i++) {
        const int row = wid + 8 * i;
        float4 v = ((const float4*)(qptr + (size_t)row * D_))[lane];
        cvtstore(v, smc + SM_QHI, smc + SM_QLO, row, lane);
        float ss = ssq4(v);
        #pragma unroll
        for (int o = 16; o > 0; o >>= 1) ss += __shfl_xor_sync(0xffffffffu, ss, o);
        if (lane == 0) invq[row] = 1.0f / fmaxf(sqrtf(ss), 1e-12f);
    }
    #pragma unroll
    for (int i = 0; i < 8; i++) {
        const int row = wid + 8 * i;
        float4 v = ((const float4*)(kptr + (size_t)row * D_))[lane];
        cvtstore(v, smc + SM_K0HI, smc + SM_K0LO, row, lane);
        float ss = ssq4(v);
        #pragma unroll
        for (int o = 16; o > 0; o >>= 1) ss += __shfl_xor_sync(0xffffffffu, ss, o);
        if (lane == 0) invk[row] = 1.0f / fmaxf(sqrtf(ss), 1e-12f);
    }
    __syncthreads();

    // ldmatrix base addresses
    const uint32_t addrA = sb + SM_QHI + (uint32_t)(qt * 16 + (lane & 15)) * ROWB
                              + (uint32_t)(16 * (lane >> 4));
    const uint32_t bcom = (uint32_t)(kh * 32 + (lane & 7) + 8 * (lane >> 4)) * ROWB
                        + (uint32_t)(16 * ((lane >> 3) & 1));
    const uint32_t addrB0 = sb + SM_K0HI + bcom;
    const uint32_t addrB1 = sb + SM_K1HI + bcom;

    float rm0 = -INFINITY, rm1 = -INFINITY;   // running per-q-row maxima

    #pragma unroll
    for (int c = 0; c < 4; c++) {
        const int p = c & 1;
        const bool pf = (c < 3);

        // 1. issue prefetch LDGs for chunk c+1 (consumed after MMA)
        float4 v[8];
        if (pf) {
            const float* kc = kptr + (size_t)(c + 1) * 64 * D_;
            #pragma unroll
            for (int i = 0; i < 8; i++)
                v[i] = ((const float4*)(kc + (size_t)(wid + 8 * i) * D_))[lane];
        }

        // 2. MMA over chunk c (buffer p)
        float acc[4][4];
        #pragma unroll
        for (int nt = 0; nt < 4; nt++)
            #pragma unroll
            for (int e = 0; e < 4; e++)
                acc[nt][e] = 0.f;

        const uint32_t aB0 = p ? addrB1 : addrB0;
        #pragma unroll
        for (int ks = 0; ks < 8; ks++) {
            uint32_t ah0, ah1, ah2, ah3, al0, al1, al2, al3;
            const uint32_t aA = addrA + ks * 32;
            LDSM_X4(ah0, ah1, ah2, ah3, aA);
            LDSM_X4(al0, al1, al2, al3, aA + DLO);
            #pragma unroll
            for (int ntp = 0; ntp < 2; ntp++) {
                uint32_t bh0, bh1, bh2, bh3, bl0, bl1, bl2, bl3;
                const uint32_t aB = aB0 + (uint32_t)(ntp * 16) * ROWB + ks * 32;
                LDSM_X4(bh0, bh1, bh2, bh3, aB);
                LDSM_X4(bl0, bl1, bl2, bl3, aB + DLO);
                MMA16816(acc[2 * ntp],     ah0, ah1, ah2, ah3, bh0, bh1);
                MMA16816(acc[2 * ntp + 1], ah0, ah1, ah2, ah3, bh2, bh3);
                MMA16816(acc[2 * ntp],     ah0, ah1, ah2, ah3, bl0, bl1);
                MMA16816(acc[2 * ntp + 1], ah0, ah1, ah2, ah3, bl2, bl3);
                MMA16816(acc[2 * ntp],     al0, al1, al2, al3, bh0, bh1);
                MMA16816(acc[2 * ntp + 1], al0, al1, al2, al3, bh2, bh3);
            }
        }

        // scale by invk (this chunk) and fold into running max
        const float* ivk = invk + p * 64;
        #pragma unroll
        for (int nt = 0; nt < 4; nt++) {
            const int kk = kh * 32 + nt * 8 + 2 * (lane & 3);
            const float ik0 = ivk[kk];
            const float ik1 = ivk[kk + 1];
            rm0 = fmaxf(rm0, fmaxf(acc[nt][0] * ik0, acc[nt][1] * ik1));
            rm1 = fmaxf(rm1, fmaxf(acc[nt][2] * ik0, acc[nt][3] * ik1));
        }

        // 3. convert + store prefetched chunk into buffer p^1, compute its invk
        if (pf) {
            char* hb = smc + (p ? SM_K0HI : SM_K1HI);
            float* ivn = invk + (p ^ 1) * 64;
            #pragma unroll
            for (int i = 0; i < 8; i++) {
                const int row = wid + 8 * i;
                cvtstore(v[i], hb, hb + DLO, row, lane);
                float ss = ssq4(v[i]);
                #pragma unroll
                for (int o = 16; o > 0; o >>= 1) ss += __shfl_xor_sync(0xffffffffu, ss, o);
                if (lane == 0) ivn[row] = 1.0f / fmaxf(sqrtf(ss), 1e-12f);
            }
        }
        __syncthreads();
    }

    // ---- reduce: max across 4-lane column group, then across key halves ----
    #pragma unroll
    for (int o = 1; o < 4; o <<= 1) {
        rm0 = fmaxf(rm0, __shfl_xor_sync(0xffffffffu, rm0, o));
        rm1 = fmaxf(rm1, __shfl_xor_sync(0xffffffffu, rm1, o));
    }
    if ((lane & 3) == 0) {
        const int row = lane >> 2;
        red[qt * 32 + row * 2 + kh]       = rm0;
        red[qt * 32 + (row + 8) * 2 + kh] = rm1;
    }
    __syncthreads();

    // ---- per-query max * invq, block-sum -> single logit ----
    float contrib = 0.f;
    if (tid < LQ) {
        const float m = fmaxf(red[tid * 2], red[tid * 2 + 1]);
        contrib = m * invq[tid];
    }
    __syncthreads();
    if (tid < LQ) {
        #pragma unroll
        for (int o = 16; o > 0; o >>= 1)
            contrib += __shfl_xor_sync(0xffffffffu, contrib, o);
        if (lane == 0) red[wid] = contrib;   // wid 0 or 1
    }
    __syncthreads();
    if (tid == 0) g_logits[cj] = red[0] + red[1];
}

// ---- finisher: log-softmax over 33 logits per batch, mean ----
__global__ void maxsim_loss_kernel(float* __restrict__ out)
{
    const int b = threadIdx.x;   // 0..31, one warp
    float mx = -INFINITY;
    float l[NC];
    #pragma unroll
    for (int j = 0; j < NC; j++) {
        l[j] = g_logits[b * NC + j] * TINV;
        mx = fmaxf(mx, l[j]);
    }
    const float l0 = l[0];
    float se = 0.f;
    #pragma unroll
    for (int j = 0; j < NC; j++) se += expf(l[j] - mx);
    float loss = (mx + logf(se)) - l0;
    #pragma unroll
    for (int off = 16; off > 0; off >>= 1)
        loss += __shfl_xor_sync(0xffffffffu, loss, off);
    if (b == 0) out[0] = loss * (1.0f / 32.0f);
}

extern "C" void kernel_launch(void* const* d_in, const int* in_sizes, int n_in,
                              void* d_out, int out_size)
{
    const float* query   = (const float*)d_in[0];
    const float* pos_key = (const float*)d_in[2];
    const float* neg_key = (const float*)d_in[4];

    cudaFuncSetAttribute(maxsim_scores_kernel,
                         cudaFuncAttributeMaxDynamicSharedMemorySize, SM_BYTES);

    maxsim_scores_kernel<<<B_ * NC, 256, SM_BYTES>>>(query, pos_key, neg_key);
    maxsim_loss_kernel<<<1, 32>>>((float*)d_out);
}